// round 14
// baseline (speedup 1.0000x reference)
#include <cuda_runtime.h>

#define BQ 64
#define NQ 64
#define TQ 4096
#define BN (BQ * NQ)     // 4096 floats per time slice
#define CCH 32           // chunks
#define LCH 128          // chunk length (CCH*LCH == TQ)

// Scratch: E = exp(emissions) in [t][b][j] layout; alpha (linear, per-(b,t)
// uniform scale — cancels in the normalized gamma).
__device__ float g_E[TQ * BN];
__device__ float g_alpha[TQ * BN];

// ---- packed f32x2 helpers ----
__device__ __forceinline__ void fma2(unsigned long long& d,
                                     unsigned long long a, unsigned long long b) {
    asm("fma.rn.f32x2 %0, %1, %2, %0;" : "+l"(d) : "l"(a), "l"(b));
}
__device__ __forceinline__ unsigned long long add2(unsigned long long a,
                                                   unsigned long long b) {
    unsigned long long d;
    asm("add.rn.f32x2 %0, %1, %2;" : "=l"(d) : "l"(a), "l"(b));
    return d;
}
__device__ __forceinline__ unsigned long long pack2(float lo, float hi) {
    unsigned long long d;
    asm("mov.b64 %0, {%1, %2};" : "=l"(d) : "f"(lo), "f"(hi));
    return d;
}
__device__ __forceinline__ float2 unpack2(unsigned long long v) {
    float2 r;
    asm("mov.b64 {%0, %1}, %2;" : "=f"(r.x), "=f"(r.y) : "l"(v));
    return r;
}

// Compiler-only memory fence: the scan block is a single CONVERGED warp, so
// smem written at step t is visible to the warp's own loads at t+1 by
// instruction order; only compiler reordering must be prevented.
#define WFENCE() asm volatile("" ::: "memory")

// ---------------------------------------------------------------------------
// Kernel 1: E[t][b][j] = exp(emissions[b][j][t])  (tiled transpose via shared)
// ---------------------------------------------------------------------------
__global__ void __launch_bounds__(256) expT_kernel(const float* __restrict__ em) {
    __shared__ float tile[64][65];
    int b  = blockIdx.y;
    int t0 = blockIdx.x * 64;
    int tid = threadIdx.x;
    int c  = tid & 63;
    int r4 = tid >> 6;

#pragma unroll
    for (int rep = 0; rep < 16; rep++) {
        int j = rep * 4 + r4;
        tile[j][c] = __expf(em[b * NQ * TQ + j * TQ + t0 + c]);
    }
    __syncthreads();
#pragma unroll
    for (int rep = 0; rep < 16; rep++) {
        int tt = rep * 4 + r4;
        g_E[(t0 + tt) * BN + b * NQ + c] = tile[c][tt];
    }
}

// ---------------------------------------------------------------------------
// Kernel 2: one warp per (chunk, batch) job; fwd scan (writes alpha) then bwd
// scan with FUSED gamma (reads own alpha — same-thread RAW, no race; emits
// out = log(a*b) - log(sum) staged in smem, flushed per 32-step window).
// Beta never touches HBM; no separate gamma kernel.
// CCH=32 -> 2048 jobs fills the 8-blocks/SM register cap (~2 warps/SMSP).
// 32 threads; thread owns states (2*tid, 2*tid+1). Renorm every 16 steps.
// E (and alpha in bwd) prefetched in 8 named float2 slots at distance 8.
// ---------------------------------------------------------------------------

#define DOT_BOTH(PBUF)                                                         \
    const ulonglong2* pv = (const ulonglong2*)&psh[PBUF][0];                   \
    unsigned long long aa0 = 0, aa1 = 0, bb0 = 0, bb1 = 0;                     \
    _Pragma("unroll")                                                          \
    for (int k = 0; k < 16; k++) {                                             \
        ulonglong2 q = pv[k];                                                  \
        fma2(aa0, q.x, ApkA[2 * k]); fma2(aa1, q.y, ApkA[2 * k + 1]);          \
        fma2(bb0, q.x, ApkB[2 * k]); fma2(bb1, q.y, ApkB[2 * k + 1]);          \
    }                                                                          \
    float2 fa = unpack2(add2(aa0, aa1));                                       \
    float2 fb = unpack2(add2(bb0, bb1));                                       \
    float va = fa.x + fa.y;                                                    \
    float vb = fb.x + fb.y;

#define REDUCE_SHFL()                                                          \
    {                                                                          \
        float s = va + vb;                                                     \
        s += __shfl_xor_sync(0xffffffffu, s, 1);                               \
        s += __shfl_xor_sync(0xffffffffu, s, 2);                               \
        s += __shfl_xor_sync(0xffffffffu, s, 4);                               \
        s += __shfl_xor_sync(0xffffffffu, s, 8);                               \
        s += __shfl_xor_sync(0xffffffffu, s, 16);                              \
        sred = s;                                                              \
    }

// Flush one 32-step output window starting at absolute time WB.
#define FLUSH_OUT(WB) do {                                                     \
    WFENCE();                                                                  \
    int ii_ = (tid & 7) * 4;                                                   \
    _Pragma("unroll")                                                          \
    for (int it_ = 0; it_ < 16; it_++) {                                       \
        int jr_ = it_ * 4 + (tid >> 3);                                        \
        float4 vv_ = make_float4(og[ii_][jr_], og[ii_ + 1][jr_],               \
                                 og[ii_ + 2][jr_], og[ii_ + 3][jr_]);          \
        *(float4*)&gout[jr_ * TQ + (WB) + ii_] = vv_;                          \
    }                                                                          \
} while (0)

// forward step at time T: consumes EREG = E2[T]; refills with E2[T+8]
#define FWD_STEP(T, EREG, APPLY, REDUCE) do {                                  \
    int tt_ = (T);                                                             \
    float2 e_new = *(const float2*)&g_E[((tt_ + 8 < TQ) ? tt_ + 8 : TQ - 1) * BN + ebase]; \
    if (APPLY) inv_s = __frcp_rn(sred);                                        \
    DOT_BOTH((tt_ - 1) & 1)                                                    \
    if (APPLY) { va *= inv_s; vb *= inv_s; }                                   \
    va *= (EREG).x; vb *= (EREG).y;                                            \
    if (REDUCE) REDUCE_SHFL()                                                  \
    if (tt_ >= wst) *(float2*)&g_alpha[tt_ * BN + ebase] = make_float2(va, vb);\
    *(float2*)&psh[tt_ & 1][j0] = make_float2(va, vb);                         \
    WFENCE();                                                                  \
    (EREG) = e_new;                                                            \
} while (0)

#define FWD_G8(TB, RED) do {                                                   \
    FWD_STEP((TB),     e7, 0, 0);   FWD_STEP((TB) + 1, e0, 0, 0);              \
    FWD_STEP((TB) + 2, e1, 0, 0);   FWD_STEP((TB) + 3, e2, 0, 0);              \
    FWD_STEP((TB) + 4, e3, 0, 0);   FWD_STEP((TB) + 5, e4, 0, 0);              \
    FWD_STEP((TB) + 6, e5, 0, RED); FWD_STEP((TB) + 7, e6, RED, 0);            \
} while (0)

// backward step at time T: EREG = E2[T] feeds the carry; AREG = alpha2[T]
// feeds the fused gamma output; both refill from T-8.
#define BWD_STEP(T, EREG, AREG, APPLY, REDUCE) do {                            \
    int tt_ = (T);                                                             \
    int tp_ = (tt_ >= 8) ? tt_ - 8 : 0;                                        \
    float2 e_new = *(const float2*)&g_E[tp_ * BN + ebase];                     \
    float2 a_new = *(const float2*)&g_alpha[tp_ * BN + ebase];                 \
    if (APPLY) inv_s = __frcp_rn(sred);                                        \
    DOT_BOTH((tt_ + 1) & 1)                                                    \
    if (APPLY) { va *= inv_s; vb *= inv_s; }                                   \
    if (REDUCE) REDUCE_SHFL()                                                  \
    if (tt_ <= wend) {                                                         \
        float ux = (AREG).x * va, uy = (AREG).y * vb;                          \
        float s2 = ux + uy;                                                    \
        s2 += __shfl_xor_sync(0xffffffffu, s2, 1);                             \
        s2 += __shfl_xor_sync(0xffffffffu, s2, 2);                             \
        s2 += __shfl_xor_sync(0xffffffffu, s2, 4);                             \
        s2 += __shfl_xor_sync(0xffffffffu, s2, 8);                             \
        s2 += __shfl_xor_sync(0xffffffffu, s2, 16);                            \
        float ls = __logf(s2);                                                 \
        *(float2*)&og[tt_ & 31][j0] =                                          \
            make_float2(__logf(ux) - ls, __logf(uy) - ls);                     \
        if ((tt_ & 31) == 0) FLUSH_OUT(tt_);                                   \
    }                                                                          \
    *(float2*)&psh[tt_ & 1][j0] = make_float2(va * (EREG).x, vb * (EREG).y);   \
    WFENCE();                                                                  \
    (EREG) = e_new;                                                            \
    (AREG) = a_new;                                                            \
} while (0)

#define BWD_G8(TB, RED) do {                                                   \
    BWD_STEP((TB),     e7, a7, 0, 0);   BWD_STEP((TB) - 1, e0, a0, 0, 0);      \
    BWD_STEP((TB) - 2, e1, a1, 0, 0);   BWD_STEP((TB) - 3, e2, a2, 0, 0);      \
    BWD_STEP((TB) - 4, e3, a3, 0, 0);   BWD_STEP((TB) - 5, e4, a4, 0, 0);      \
    BWD_STEP((TB) - 6, e5, a5, 0, RED); BWD_STEP((TB) - 7, e6, a6, RED, 0);    \
} while (0)

__global__ void __launch_bounds__(32) scan_kernel(const float* __restrict__ trans,
                                                  const float* __restrict__ init,
                                                  float* __restrict__ out) {
    const int c   = blockIdx.x;      // chunk
    const int b   = blockIdx.y;      // batch
    const int tid = threadIdx.x;     // 0..31
    const int j0  = 2 * tid;         // first of the two owned states

    __shared__ __align__(16) float psh[2][64];
    __shared__ __align__(16) float og[32][66];   // staged output window

    unsigned long long ApkA[32], ApkB[32];
    const int ebase = b * NQ + j0;   // even -> float2-aligned
    float* gout = out + b * NQ * TQ;
    float inv_s = 1.0f;
    float sred  = 1.0f;

    // ================= Phase 1: forward =================
    // columns j0, j0+1 of A
#pragma unroll
    for (int k = 0; k < 16; k++) {
        int i0 = 4 * k;
        ApkA[2 * k]     = pack2(trans[(i0    ) * NQ + j0], trans[(i0 + 1) * NQ + j0]);
        ApkA[2 * k + 1] = pack2(trans[(i0 + 2) * NQ + j0], trans[(i0 + 3) * NQ + j0]);
        ApkB[2 * k]     = pack2(trans[(i0    ) * NQ + j0 + 1], trans[(i0 + 1) * NQ + j0 + 1]);
        ApkB[2 * k + 1] = pack2(trans[(i0 + 2) * NQ + j0 + 1], trans[(i0 + 3) * NQ + j0 + 1]);
    }
    {
        const int wst = c * LCH;
        int t1, Gp, Gr;
        if (c == 0) {
            float2 ee = *(const float2*)&g_E[0 * BN + ebase];
            float2 v0 = make_float2(init[j0] * ee.x, init[j0 + 1] * ee.y);
            *(float2*)&g_alpha[0 * BN + ebase] = v0;
            *(float2*)&psh[0][j0] = v0;
            t1 = 1;  Gp = 7;  Gr = 1;        // 7 + 15*8 = 127 steps: t = 1..127
        } else {
            t1 = c * LCH - 39;               // 39-step warmup from all-ones
            *(float2*)&psh[(t1 - 1) & 1][j0] = make_float2(1.0f, 1.0f);
            Gp = 10;  Gr = 0;                // 7 + 20*8 = 167 steps
        }
        float2 e0 = *(const float2*)&g_E[(t1    ) * BN + ebase];
        float2 e1 = *(const float2*)&g_E[(t1 + 1) * BN + ebase];
        float2 e2 = *(const float2*)&g_E[(t1 + 2) * BN + ebase];
        float2 e3 = *(const float2*)&g_E[(t1 + 3) * BN + ebase];
        float2 e4 = *(const float2*)&g_E[(t1 + 4) * BN + ebase];
        float2 e5 = *(const float2*)&g_E[(t1 + 5) * BN + ebase];
        float2 e6 = *(const float2*)&g_E[(t1 + 6) * BN + ebase];
        float2 e7 = *(const float2*)&g_E[(t1 + 7) * BN + ebase];
        WFENCE();

        FWD_STEP(t1,     e0, 0, 0); FWD_STEP(t1 + 1, e1, 0, 0);
        FWD_STEP(t1 + 2, e2, 0, 0); FWD_STEP(t1 + 3, e3, 0, 0);
        FWD_STEP(t1 + 4, e4, 0, 0); FWD_STEP(t1 + 5, e5, 0, 0);
        FWD_STEP(t1 + 6, e6, 0, 0);

        for (int p = 0; p < Gp; p++) {       // pairs: renorm in 2nd group only
            int t = t1 + 7 + 16 * p;
            FWD_G8(t, 0); FWD_G8(t + 8, 1);
        }
        for (int g = 0; g < Gr; g++) {
            int t = t1 + 7 + 16 * Gp + 8 * g;
            FWD_G8(t, 1);
        }
    }

    // ================= Phase 2: backward + fused gamma =================
    // rows j0, j0+1 of A (contiguous)
    {
        const float4* rA = (const float4*)(trans + j0 * NQ);
        const float4* rB = (const float4*)(trans + (j0 + 1) * NQ);
#pragma unroll
        for (int k = 0; k < 16; k++) {
            float4 a = rA[k];
            ApkA[2 * k]     = pack2(a.x, a.y);
            ApkA[2 * k + 1] = pack2(a.z, a.w);
            float4 bq = rB[k];
            ApkB[2 * k]     = pack2(bq.x, bq.y);
            ApkB[2 * k + 1] = pack2(bq.z, bq.w);
        }
    }
    {
        const int wend = (c + 1) * LCH - 1;
        int te, Gp, Gr;
        if (c == CCH - 1) {
            te = TQ - 1;
            // t = TQ-1: beta = 1 -> u = alpha; stage its output row now.
            float2 aT = *(const float2*)&g_alpha[te * BN + ebase];
            float ux = aT.x, uy = aT.y;
            float s2 = ux + uy;
            s2 += __shfl_xor_sync(0xffffffffu, s2, 1);
            s2 += __shfl_xor_sync(0xffffffffu, s2, 2);
            s2 += __shfl_xor_sync(0xffffffffu, s2, 4);
            s2 += __shfl_xor_sync(0xffffffffu, s2, 8);
            s2 += __shfl_xor_sync(0xffffffffu, s2, 16);
            float ls = __logf(s2);
            *(float2*)&og[31][j0] = make_float2(__logf(ux) - ls, __logf(uy) - ls);
            *(float2*)&psh[te & 1][j0] = *(const float2*)&g_E[te * BN + ebase];
            Gp = 7;  Gr = 1;                         // 127 steps
        } else {
            te = (c + 1) * LCH + 39;                 // warmup start
            *(float2*)&psh[te & 1][j0] = *(const float2*)&g_E[te * BN + ebase];
            Gp = 10;  Gr = 0;                        // 167 steps
        }
        int t1 = te - 1;
        float2 e0 = *(const float2*)&g_E[(t1    ) * BN + ebase];
        float2 e1 = *(const float2*)&g_E[(t1 - 1) * BN + ebase];
        float2 e2 = *(const float2*)&g_E[(t1 - 2) * BN + ebase];
        float2 e3 = *(const float2*)&g_E[(t1 - 3) * BN + ebase];
        float2 e4 = *(const float2*)&g_E[(t1 - 4) * BN + ebase];
        float2 e5 = *(const float2*)&g_E[(t1 - 5) * BN + ebase];
        float2 e6 = *(const float2*)&g_E[(t1 - 6) * BN + ebase];
        float2 e7 = *(const float2*)&g_E[(t1 - 7) * BN + ebase];
        float2 a0 = *(const float2*)&g_alpha[(t1    ) * BN + ebase];
        float2 a1 = *(const float2*)&g_alpha[(t1 - 1) * BN + ebase];
        float2 a2 = *(const float2*)&g_alpha[(t1 - 2) * BN + ebase];
        float2 a3 = *(const float2*)&g_alpha[(t1 - 3) * BN + ebase];
        float2 a4 = *(const float2*)&g_alpha[(t1 - 4) * BN + ebase];
        float2 a5 = *(const float2*)&g_alpha[(t1 - 5) * BN + ebase];
        float2 a6 = *(const float2*)&g_alpha[(t1 - 6) * BN + ebase];
        float2 a7 = *(const float2*)&g_alpha[(t1 - 7) * BN + ebase];
        WFENCE();

        BWD_STEP(t1,     e0, a0, 0, 0); BWD_STEP(t1 - 1, e1, a1, 0, 0);
        BWD_STEP(t1 - 2, e2, a2, 0, 0); BWD_STEP(t1 - 3, e3, a3, 0, 0);
        BWD_STEP(t1 - 4, e4, a4, 0, 0); BWD_STEP(t1 - 5, e5, a5, 0, 0);
        BWD_STEP(t1 - 6, e6, a6, 0, 0);

        for (int p = 0; p < Gp; p++) {
            int t = t1 - 7 - 16 * p;
            BWD_G8(t, 0); BWD_G8(t - 8, 1);
        }
        for (int g = 0; g < Gr; g++) {
            int t = t1 - 7 - 16 * Gp - 8 * g;
            BWD_G8(t, 1);
        }
    }
}

// ---------------------------------------------------------------------------
extern "C" void kernel_launch(void* const* d_in, const int* in_sizes, int n_in,
                              void* d_out, int out_size) {
    const float* emissions = (const float*)d_in[0];   // [B, N, T]
    const float* init      = (const float*)d_in[1];   // [N]
    const float* trans     = (const float*)d_in[2];   // [N, N]
    float* out = (float*)d_out;                       // [B, N, T]

    expT_kernel<<<dim3(TQ / 64, BQ), 256>>>(emissions);
    scan_kernel<<<dim3(CCH, BQ), 32>>>(trans, init, out);
}

// round 16
// speedup vs baseline: 1.1618x; 1.1618x over previous
#include <cuda_runtime.h>

#define BQ 64
#define NQ 64
#define TQ 4096
#define BN (BQ * NQ)     // 4096 floats per time slice
#define CCH 16           // chunks
#define LCH 256          // chunk length (CCH*LCH == TQ)

// Scratch: E = exp(emissions) in [t][b][j] layout, plus linear-domain
// alpha/beta (arbitrary per-(b,t) scale; cancels in gamma).
__device__ float g_E[TQ * BN];
__device__ float g_alpha[TQ * BN];
__device__ float g_beta[TQ * BN];

// ---- packed f32x2 helpers ----
__device__ __forceinline__ void fma2(unsigned long long& d,
                                     unsigned long long a, unsigned long long b) {
    asm("fma.rn.f32x2 %0, %1, %2, %0;" : "+l"(d) : "l"(a), "l"(b));
}
__device__ __forceinline__ unsigned long long add2(unsigned long long a,
                                                   unsigned long long b) {
    unsigned long long d;
    asm("add.rn.f32x2 %0, %1, %2;" : "=l"(d) : "l"(a), "l"(b));
    return d;
}
__device__ __forceinline__ unsigned long long pack2(float lo, float hi) {
    unsigned long long d;
    asm("mov.b64 %0, {%1, %2};" : "=l"(d) : "f"(lo), "f"(hi));
    return d;
}
__device__ __forceinline__ float2 unpack2(unsigned long long v) {
    float2 r;
    asm("mov.b64 {%0, %1}, %2;" : "=f"(r.x), "=f"(r.y) : "l"(v));
    return r;
}

// ---------------------------------------------------------------------------
// Kernel 1: E[t][b][j] = exp(emissions[b][j][t])  (tiled transpose via shared)
// ---------------------------------------------------------------------------
__global__ void __launch_bounds__(256) expT_kernel(const float* __restrict__ em) {
    __shared__ float tile[64][65];
    int b  = blockIdx.y;
    int t0 = blockIdx.x * 64;
    int tid = threadIdx.x;
    int c  = tid & 63;
    int r4 = tid >> 6;

#pragma unroll
    for (int rep = 0; rep < 16; rep++) {
        int j = rep * 4 + r4;
        tile[j][c] = __expf(em[b * NQ * TQ + j * TQ + t0 + c]);
    }
    __syncthreads();
#pragma unroll
    for (int rep = 0; rep < 16; rep++) {
        int tt = rep * 4 + r4;
        g_E[(t0 + tt) * BN + b * NQ + c] = tile[c][tt];
    }
}

// ---------------------------------------------------------------------------
// Kernel 2: chunked forward/backward scans with warmup (combined concurrent
// launch — champion R12 structure). 32 threads/block; thread owns ADJACENT
// states (2*tid, 2*tid+1); shared-vector LDS.128 are uniform (broadcast) and
// feed both states' dots. 8 accumulators per 2-state dot -> fma2 dependency
// chains of 8 (halved vs R12) to cut per-step latency.
// Interior chunks warm up 39 steps from all-ones (Hilbert contraction of A).
// Renorm every 16 steps, pipelined. E prefetch: 8 named float2 slots.
// ---------------------------------------------------------------------------

#define DOT_BOTH(PBUF)                                                         \
    const ulonglong2* pv = (const ulonglong2*)&psh[PBUF][0];                   \
    unsigned long long aa0 = 0, aa1 = 0, aa2 = 0, aa3 = 0;                     \
    unsigned long long bb0 = 0, bb1 = 0, bb2 = 0, bb3 = 0;                     \
    _Pragma("unroll")                                                          \
    for (int k = 0; k < 16; k += 2) {                                          \
        ulonglong2 q0 = pv[k];                                                 \
        ulonglong2 q1 = pv[k + 1];                                             \
        fma2(aa0, q0.x, ApkA[2 * k]);     fma2(aa1, q0.y, ApkA[2 * k + 1]);    \
        fma2(bb0, q0.x, ApkB[2 * k]);     fma2(bb1, q0.y, ApkB[2 * k + 1]);    \
        fma2(aa2, q1.x, ApkA[2 * k + 2]); fma2(aa3, q1.y, ApkA[2 * k + 3]);    \
        fma2(bb2, q1.x, ApkB[2 * k + 2]); fma2(bb3, q1.y, ApkB[2 * k + 3]);    \
    }                                                                          \
    float2 fa = unpack2(add2(add2(aa0, aa1), add2(aa2, aa3)));                 \
    float2 fb = unpack2(add2(add2(bb0, bb1), add2(bb2, bb3)));                 \
    float va = fa.x + fa.y;                                                    \
    float vb = fb.x + fb.y;

#define REDUCE_SHFL()                                                          \
    {                                                                          \
        float s = va + vb;                                                     \
        s += __shfl_xor_sync(0xffffffffu, s, 1);                               \
        s += __shfl_xor_sync(0xffffffffu, s, 2);                               \
        s += __shfl_xor_sync(0xffffffffu, s, 4);                               \
        s += __shfl_xor_sync(0xffffffffu, s, 8);                               \
        s += __shfl_xor_sync(0xffffffffu, s, 16);                              \
        sred = s;                                                              \
    }

// forward step at time T: consumes EREG = E2[T]; refills with E2[T+8]
#define FWD_STEP(T, EREG, APPLY, REDUCE) do {                                  \
    int tt_ = (T);                                                             \
    float2 e_new = *(const float2*)&g_E[((tt_ + 8 < TQ) ? tt_ + 8 : TQ - 1) * BN + ebase]; \
    if (APPLY) inv_s = __frcp_rn(sred);                                        \
    DOT_BOTH((tt_ - 1) & 1)                                                    \
    if (APPLY) { va *= inv_s; vb *= inv_s; }                                   \
    va *= (EREG).x; vb *= (EREG).y;                                            \
    if (REDUCE) REDUCE_SHFL()                                                  \
    if (tt_ >= wst) *(float2*)&g_alpha[tt_ * BN + ebase] = make_float2(va, vb);\
    *(float2*)&psh[tt_ & 1][j0] = make_float2(va, vb);                         \
    __syncwarp();                                                              \
    (EREG) = e_new;                                                            \
} while (0)

#define FWD_G8(TB, RED) do {                                                   \
    FWD_STEP((TB),     e7, 0, 0);   FWD_STEP((TB) + 1, e0, 0, 0);              \
    FWD_STEP((TB) + 2, e1, 0, 0);   FWD_STEP((TB) + 3, e2, 0, 0);              \
    FWD_STEP((TB) + 4, e3, 0, 0);   FWD_STEP((TB) + 5, e4, 0, 0);              \
    FWD_STEP((TB) + 6, e5, 0, RED); FWD_STEP((TB) + 7, e6, RED, 0);            \
} while (0)

// backward step at time T: EREG = E2[T] feeds the carry; refills with E2[T-8]
#define BWD_STEP(T, EREG, APPLY, REDUCE) do {                                  \
    int tt_ = (T);                                                             \
    float2 e_new = *(const float2*)&g_E[((tt_ >= 8) ? tt_ - 8 : 0) * BN + ebase]; \
    if (APPLY) inv_s = __frcp_rn(sred);                                        \
    DOT_BOTH((tt_ + 1) & 1)                                                    \
    if (APPLY) { va *= inv_s; vb *= inv_s; }                                   \
    if (REDUCE) REDUCE_SHFL()                                                  \
    if (tt_ <= wend) *(float2*)&g_beta[tt_ * BN + ebase] = make_float2(va, vb);\
    *(float2*)&psh[tt_ & 1][j0] = make_float2(va * (EREG).x, vb * (EREG).y);   \
    __syncwarp();                                                              \
    (EREG) = e_new;                                                            \
} while (0)

#define BWD_G8(TB, RED) do {                                                   \
    BWD_STEP((TB),     e7, 0, 0);   BWD_STEP((TB) - 1, e0, 0, 0);              \
    BWD_STEP((TB) - 2, e1, 0, 0);   BWD_STEP((TB) - 3, e2, 0, 0);              \
    BWD_STEP((TB) - 4, e3, 0, 0);   BWD_STEP((TB) - 5, e4, 0, 0);              \
    BWD_STEP((TB) - 6, e5, 0, RED); BWD_STEP((TB) - 7, e6, RED, 0);            \
} while (0)

__global__ void __launch_bounds__(32) scan_kernel(const float* __restrict__ trans,
                                                  const float* __restrict__ init) {
    const int c   = blockIdx.x;      // chunk
    const int b   = blockIdx.y;      // batch
    const int dir = blockIdx.z;      // 0 fwd, 1 bwd
    const int tid = threadIdx.x;     // 0..31
    const int j0  = 2 * tid;         // first of the two owned states

    __shared__ __align__(16) float psh[2][64];

    // Two columns (fwd) or two rows (bwd) of A, packed: 64 u64 registers.
    unsigned long long ApkA[32], ApkB[32];
    if (dir == 0) {
        // fwd: columns j0, j0+1 of A
#pragma unroll
        for (int k = 0; k < 16; k++) {
            int i0 = 4 * k;
            ApkA[2 * k]     = pack2(trans[(i0    ) * NQ + j0], trans[(i0 + 1) * NQ + j0]);
            ApkA[2 * k + 1] = pack2(trans[(i0 + 2) * NQ + j0], trans[(i0 + 3) * NQ + j0]);
            ApkB[2 * k]     = pack2(trans[(i0    ) * NQ + j0 + 1], trans[(i0 + 1) * NQ + j0 + 1]);
            ApkB[2 * k + 1] = pack2(trans[(i0 + 2) * NQ + j0 + 1], trans[(i0 + 3) * NQ + j0 + 1]);
        }
    } else {
        // bwd: rows j0, j0+1 of A (contiguous)
        const float4* rA = (const float4*)(trans + j0 * NQ);
        const float4* rB = (const float4*)(trans + (j0 + 1) * NQ);
#pragma unroll
        for (int k = 0; k < 16; k++) {
            float4 a = rA[k];
            ApkA[2 * k]     = pack2(a.x, a.y);
            ApkA[2 * k + 1] = pack2(a.z, a.w);
            float4 bq = rB[k];
            ApkB[2 * k]     = pack2(bq.x, bq.y);
            ApkB[2 * k + 1] = pack2(bq.z, bq.w);
        }
    }

    const int ebase = b * NQ + j0;   // even -> float2-aligned
    float inv_s = 1.0f;
    float sred  = 1.0f;

    if (dir == 0) {
        // -------- forward: write t in [c*L, (c+1)*L) --------
        const int wst = c * LCH;
        int t1, Gp, Gr;
        if (c == 0) {
            float2 ee = *(const float2*)&g_E[0 * BN + ebase];
            float2 v0 = make_float2(init[j0] * ee.x, init[j0 + 1] * ee.y);
            *(float2*)&g_alpha[0 * BN + ebase] = v0;
            *(float2*)&psh[0][j0] = v0;
            t1 = 1;  Gp = 15;  Gr = 1;       // 7 + 31*8 = 255 steps: t = 1..255
        } else {
            t1 = c * LCH - 39;               // 39-step warmup from all-ones
            *(float2*)&psh[(t1 - 1) & 1][j0] = make_float2(1.0f, 1.0f);
            Gp = 18;  Gr = 0;                // 7 + 36*8 = 295 steps
        }
        float2 e0 = *(const float2*)&g_E[(t1    ) * BN + ebase];
        float2 e1 = *(const float2*)&g_E[(t1 + 1) * BN + ebase];
        float2 e2 = *(const float2*)&g_E[(t1 + 2) * BN + ebase];
        float2 e3 = *(const float2*)&g_E[(t1 + 3) * BN + ebase];
        float2 e4 = *(const float2*)&g_E[(t1 + 4) * BN + ebase];
        float2 e5 = *(const float2*)&g_E[(t1 + 5) * BN + ebase];
        float2 e6 = *(const float2*)&g_E[(t1 + 6) * BN + ebase];
        float2 e7 = *(const float2*)&g_E[(t1 + 7) * BN + ebase];
        __syncwarp();

        // INIT7 (no renorm)
        FWD_STEP(t1,     e0, 0, 0); FWD_STEP(t1 + 1, e1, 0, 0);
        FWD_STEP(t1 + 2, e2, 0, 0); FWD_STEP(t1 + 3, e3, 0, 0);
        FWD_STEP(t1 + 4, e4, 0, 0); FWD_STEP(t1 + 5, e5, 0, 0);
        FWD_STEP(t1 + 6, e6, 0, 0);

        for (int p = 0; p < Gp; p++) {       // pairs: renorm in 2nd group only
            int t = t1 + 7 + 16 * p;
            FWD_G8(t, 0); FWD_G8(t + 8, 1);
        }
        for (int g = 0; g < Gr; g++) {       // remainder groups renorm each
            int t = t1 + 7 + 16 * Gp + 8 * g;
            FWD_G8(t, 1);
        }
    } else {
        // -------- backward: write t in [c*L, (c+1)*L) --------
        const int wend = (c + 1) * LCH - 1;
        int te, Gp, Gr;
        if (c == CCH - 1) {
            te = TQ - 1;
            *(float2*)&g_beta[te * BN + ebase] = make_float2(1.0f, 1.0f);
            *(float2*)&psh[te & 1][j0] = *(const float2*)&g_E[te * BN + ebase];
            Gp = 15;  Gr = 1;                        // 255 steps
        } else {
            te = (c + 1) * LCH + 39;                 // warmup start
            *(float2*)&psh[te & 1][j0] = *(const float2*)&g_E[te * BN + ebase];
            Gp = 18;  Gr = 0;                        // 295 steps
        }
        int t1 = te - 1;
        float2 e0 = *(const float2*)&g_E[(t1    ) * BN + ebase];
        float2 e1 = *(const float2*)&g_E[(t1 - 1) * BN + ebase];
        float2 e2 = *(const float2*)&g_E[(t1 - 2) * BN + ebase];
        float2 e3 = *(const float2*)&g_E[(t1 - 3) * BN + ebase];
        float2 e4 = *(const float2*)&g_E[(t1 - 4) * BN + ebase];
        float2 e5 = *(const float2*)&g_E[(t1 - 5) * BN + ebase];
        float2 e6 = *(const float2*)&g_E[(t1 - 6) * BN + ebase];
        float2 e7 = *(const float2*)&g_E[(t1 - 7) * BN + ebase];
        __syncwarp();

        // INIT7 (no renorm)
        BWD_STEP(t1,     e0, 0, 0); BWD_STEP(t1 - 1, e1, 0, 0);
        BWD_STEP(t1 - 2, e2, 0, 0); BWD_STEP(t1 - 3, e3, 0, 0);
        BWD_STEP(t1 - 4, e4, 0, 0); BWD_STEP(t1 - 5, e5, 0, 0);
        BWD_STEP(t1 - 6, e6, 0, 0);

        for (int p = 0; p < Gp; p++) {
            int t = t1 - 7 - 16 * p;
            BWD_G8(t, 0); BWD_G8(t - 8, 1);
        }
        for (int g = 0; g < Gr; g++) {
            int t = t1 - 7 - 16 * Gp - 8 * g;
            BWD_G8(t, 1);
        }
    }
}

// ---------------------------------------------------------------------------
// Kernel 3: gamma, linear domain. u = alpha*beta;
// out = log(u) - log(sum_j u).  (NOTE: the log on u is load-bearing — its
// omission was the R15 correctness failure.)
// ---------------------------------------------------------------------------
__global__ void __launch_bounds__(256) gamma_kernel(float* __restrict__ out) {
    __shared__ float gsh[64][33];
    __shared__ float part[8][32];
    __shared__ float lse[32];

    int b   = blockIdx.y;
    int t0  = blockIdx.x * 32;
    int tid = threadIdx.x;
    int c   = tid & 63;
    int r   = tid >> 6;

#pragma unroll
    for (int rep = 0; rep < 8; rep++) {
        int tt  = rep * 4 + r;
        int idx = (t0 + tt) * BN + b * NQ + c;
        gsh[c][tt] = g_alpha[idx] * g_beta[idx];
    }
    __syncthreads();

    int tt  = tid & 31;
    int seg = tid >> 5;

    float ss = 0.f;
#pragma unroll
    for (int k = 0; k < 8; k++) ss += gsh[seg * 8 + k][tt];
    part[seg][tt] = ss;
    __syncthreads();

    if (seg == 0) {
        float s = part[0][tt];
#pragma unroll
        for (int k = 1; k < 8; k++) s += part[k][tt];
        lse[tt] = __logf(s);
    }
    __syncthreads();

    float l = lse[tt];
#pragma unroll
    for (int rep = 0; rep < 8; rep++) {
        int jj = rep * 8 + seg;
        out[b * NQ * TQ + jj * TQ + t0 + tt] = __logf(gsh[jj][tt]) - l;
    }
}

// ---------------------------------------------------------------------------
extern "C" void kernel_launch(void* const* d_in, const int* in_sizes, int n_in,
                              void* d_out, int out_size) {
    const float* emissions = (const float*)d_in[0];   // [B, N, T]
    const float* init      = (const float*)d_in[1];   // [N]
    const float* trans     = (const float*)d_in[2];   // [N, N]
    float* out = (float*)d_out;                       // [B, N, T]

    expT_kernel<<<dim3(TQ / 64, BQ), 256>>>(emissions);
    scan_kernel<<<dim3(CCH, BQ, 2), 32>>>(trans, init);
    gamma_kernel<<<dim3(TQ / 32, BQ), 256>>>(out);
}